// round 5
// baseline (speedup 1.0000x reference)
#include <cuda_runtime.h>
#include <math.h>
#include <stdint.h>

#define IN_DIM  256
#define OUT_DIM 256   // H*D = 4*64
#define NHEAD   4
#define NMAX    50000
#define EMAX    800000
#define ETOTMAX (EMAX + NMAX)

// ---------------- scratch (__device__ globals; allocation-free) ----------------
__device__ float    g_h[(size_t)NMAX * OUT_DIM];     // 51.2 MB transformed features
__device__ float    g_as[NMAX * NHEAD];
__device__ float    g_ad[NMAX * NHEAD];
__device__ int      g_cnt[NMAX];
__device__ int      g_fill[NMAX];
__device__ int      g_start[NMAX + 1];
__device__ int      g_csr[ETOTMAX];
__device__ float    g_w[(size_t)ETOTMAX * NHEAD];
__device__ float    g_s[NMAX * NHEAD];
__device__ unsigned g_wh[IN_DIM * OUT_DIM];          // W hi (tf32 bits), [k][n]
__device__ unsigned g_wl[IN_DIM * OUT_DIM];          // W lo residual (tf32 bits), [k][n]

__device__ __forceinline__ unsigned tf32_bits(float f) {
    unsigned r; asm("cvt.rna.tf32.f32 %0, %1;" : "=r"(r) : "f"(f)); return r;
}

__device__ __forceinline__ void mma_tf32(float* c, uint32_t a0, uint32_t a1,
                                         uint32_t a2, uint32_t a3,
                                         uint32_t b0, uint32_t b1) {
    asm("mma.sync.aligned.m16n8k8.row.col.f32.tf32.tf32.f32 "
        "{%0,%1,%2,%3},{%4,%5,%6,%7},{%8,%9},{%0,%1,%2,%3};"
        : "+f"(c[0]), "+f"(c[1]), "+f"(c[2]), "+f"(c[3])
        : "r"(a0), "r"(a1), "r"(a2), "r"(a3), "r"(b0), "r"(b1));
}

__device__ __forceinline__ float lrelu(float x) { return x > 0.f ? x : 0.2f * x; }
__device__ __forceinline__ float4 lrelu4(float4 a) {
    return make_float4(lrelu(a.x), lrelu(a.y), lrelu(a.z), lrelu(a.w));
}
__device__ __forceinline__ float4 add4(float4 a, float4 b) {
    return make_float4(a.x + b.x, a.y + b.y, a.z + b.z, a.w + b.w);
}
__device__ __forceinline__ float4 max4(float4 a, float4 b) {
    return make_float4(fmaxf(a.x, b.x), fmaxf(a.y, b.y), fmaxf(a.z, b.z), fmaxf(a.w, b.w));
}

// ---------------- K0: zero counters ----------------
__global__ void k_zero(int N) {
    int stride = gridDim.x * blockDim.x;
    for (int i = blockIdx.x * blockDim.x + threadIdx.x; i < 2 * N; i += stride) {
        if (i < N) g_cnt[i] = 0; else g_fill[i - N] = 0;
    }
}

// ---------------- K0b: W -> tf32 hi/lo split, [k][n] layout kept ----------------
__global__ void k_wt(const float* __restrict__ W) {
    int idx = blockIdx.x * blockDim.x + threadIdx.x;
    if (idx >= IN_DIM * OUT_DIM) return;
    float w = W[idx];
    unsigned hi = tf32_bits(w);
    unsigned lo = tf32_bits(w - __uint_as_float(hi));
    g_wh[idx] = hi;
    g_wl[idx] = lo;
}

// ---------------- K1: GEMM h = x @ W via mma.sync tf32, 2-pass W split ----------------
// BM=128, BN=128, BK=32; 8 warps, warp tile 32x64.
#define XS_STRIDE 36
#define WS_STRIDE 132
#define SM_XS 0
#define SM_WH (128 * XS_STRIDE)                   // 4608 floats
#define SM_WL (SM_WH + 32 * WS_STRIDE)            // +4224
#define SM_GEMM_BYTES ((SM_WL + 32 * WS_STRIDE) * 4)   // 52224 B
__global__ __launch_bounds__(256) void k_gemm_mma(const float* __restrict__ x, int N) {
    extern __shared__ unsigned smem[];
    unsigned* xs  = smem + SM_XS;   // [128][36] tf32 bits
    unsigned* wsh = smem + SM_WH;   // [32][132]
    unsigned* wsl = smem + SM_WL;   // [32][132]

    int tid = threadIdx.x;
    int wid = tid >> 5, lane = tid & 31;
    int g = lane >> 2, t = lane & 3;
    int m0 = blockIdx.x * 128;
    int n0 = blockIdx.y * 128;
    int wm = (wid & 3) * 32;        // warp row offset in CTA tile
    int wn = (wid >> 2) * 64;       // warp col offset in CTA tile

    float acc[2][8][4];
#pragma unroll
    for (int mt = 0; mt < 2; mt++)
#pragma unroll
        for (int nt = 0; nt < 8; nt++)
#pragma unroll
            for (int i = 0; i < 4; i++) acc[mt][nt][i] = 0.f;

    int xrow = tid >> 1;                 // 0..127
    int xkq  = (tid & 1) * 16;           // 0 or 16
    int wrow = tid >> 3;                 // 0..31
    int wcq  = (tid & 7) * 16;           // 0..112

    for (int k0 = 0; k0 < IN_DIM; k0 += 32) {
        // load x tile [128][32] -> tf32
        {
            int grow = m0 + xrow;
            const float4* xr = (const float4*)&x[(size_t)grow * IN_DIM + k0 + xkq];
#pragma unroll
            for (int i = 0; i < 4; i++) {
                float4 v = (grow < N) ? xr[i] : make_float4(0.f, 0.f, 0.f, 0.f);
                uint4 b = make_uint4(tf32_bits(v.x), tf32_bits(v.y),
                                     tf32_bits(v.z), tf32_bits(v.w));
                *(uint4*)&xs[xrow * XS_STRIDE + xkq + i * 4] = b;
            }
        }
        // load W hi/lo tiles [32][128]
        {
            const uint4* wh = (const uint4*)&g_wh[(size_t)(k0 + wrow) * OUT_DIM + n0 + wcq];
            const uint4* wl = (const uint4*)&g_wl[(size_t)(k0 + wrow) * OUT_DIM + n0 + wcq];
#pragma unroll
            for (int i = 0; i < 4; i++) {
                *(uint4*)&wsh[wrow * WS_STRIDE + wcq + i * 4] = wh[i];
                *(uint4*)&wsl[wrow * WS_STRIDE + wcq + i * 4] = wl[i];
            }
        }
        __syncthreads();

#pragma unroll
        for (int kk = 0; kk < 32; kk += 8) {
            // A fragments (2 m-tiles)
            uint32_t a[2][4];
#pragma unroll
            for (int mt = 0; mt < 2; mt++) {
                int rbase = (wm + mt * 16 + g) * XS_STRIDE + kk;
                a[mt][0] = xs[rbase + t];
                a[mt][1] = xs[rbase + 8 * XS_STRIDE + t];
                a[mt][2] = xs[rbase + t + 4];
                a[mt][3] = xs[rbase + 8 * XS_STRIDE + t + 4];
            }
#pragma unroll
            for (int nt = 0; nt < 8; nt++) {
                int cb = (kk + t) * WS_STRIDE + wn + nt * 8 + g;
                uint32_t bh0 = wsh[cb], bh1 = wsh[cb + 4 * WS_STRIDE];
                uint32_t bl0 = wsl[cb], bl1 = wsl[cb + 4 * WS_STRIDE];
#pragma unroll
                for (int mt = 0; mt < 2; mt++) {
                    mma_tf32(acc[mt][nt], a[mt][0], a[mt][1], a[mt][2], a[mt][3], bh0, bh1);
                    mma_tf32(acc[mt][nt], a[mt][0], a[mt][1], a[mt][2], a[mt][3], bl0, bl1);
                }
            }
        }
        __syncthreads();
    }

    // store: acc[mt][nt][0..3] -> rows (g, g+8) of m-tile, cols 2t,2t+1 of n-tile
#pragma unroll
    for (int mt = 0; mt < 2; mt++) {
        int r0 = m0 + wm + mt * 16 + g;
        int r1 = r0 + 8;
#pragma unroll
        for (int nt = 0; nt < 8; nt++) {
            int c = n0 + wn + nt * 8 + 2 * t;
            if (r0 < N) *(float2*)&g_h[(size_t)r0 * OUT_DIM + c] =
                make_float2(acc[mt][nt][0], acc[mt][nt][1]);
            if (r1 < N) *(float2*)&g_h[(size_t)r1 * OUT_DIM + c] =
                make_float2(acc[mt][nt][2], acc[mt][nt][3]);
        }
    }
}

// ---------------- K2: per-node attention logits (one warp per node) ----------------
__global__ void k_att(const float* __restrict__ att_src, const float* __restrict__ att_dst, int N) {
    int warp = (blockIdx.x * blockDim.x + threadIdx.x) >> 5;
    int lane = threadIdx.x & 31;
    if (warp >= N) return;
    const float* hp = &g_h[(size_t)warp * OUT_DIM + lane * 8];
    float4 a0 = *(const float4*)hp;
    float4 a1 = *(const float4*)(hp + 4);
    float4 s0 = *(const float4*)&att_src[lane * 8];
    float4 s1 = *(const float4*)&att_src[lane * 8 + 4];
    float4 d0 = *(const float4*)&att_dst[lane * 8];
    float4 d1 = *(const float4*)&att_dst[lane * 8 + 4];
    float ss = a0.x*s0.x + a0.y*s0.y + a0.z*s0.z + a0.w*s0.w
             + a1.x*s1.x + a1.y*s1.y + a1.z*s1.z + a1.w*s1.w;
    float sd = a0.x*d0.x + a0.y*d0.y + a0.z*d0.z + a0.w*d0.w
             + a1.x*d1.x + a1.y*d1.y + a1.z*d1.z + a1.w*d1.w;
#pragma unroll
    for (int off = 4; off >= 1; off >>= 1) {
        ss += __shfl_down_sync(0xffffffffu, ss, off, 8);
        sd += __shfl_down_sync(0xffffffffu, sd, off, 8);
    }
    if ((lane & 7) == 0) {
        int head = lane >> 3;
        g_as[warp * NHEAD + head] = ss;
        g_ad[warp * NHEAD + head] = sd;
    }
}

// ---------------- K3a: histogram of dst ----------------
__global__ void k_hist(const int* __restrict__ ei, int E, int N) {
    int Etot = E + N;
    int stride = gridDim.x * blockDim.x;
    for (int i = blockIdx.x * blockDim.x + threadIdx.x; i < Etot; i += stride) {
        int dst = (i < E) ? ei[E + i] : (i - E);
        atomicAdd(&g_cnt[dst], 1);
    }
}

// ---------------- K3b: exclusive scan (single block) ----------------
__global__ __launch_bounds__(1024) void k_scan(int N) {
    __shared__ int wsum[32];
    int tid = threadIdx.x;
    int chunk = (N + 1023) >> 10;
    int base = tid * chunk;
    int local = 0;
    for (int i = 0; i < chunk; i++) {
        int idx = base + i;
        if (idx < N) local += g_cnt[idx];
    }
    int lane = tid & 31, w = tid >> 5;
    int v = local;
#pragma unroll
    for (int off = 1; off < 32; off <<= 1) {
        int t = __shfl_up_sync(0xffffffffu, v, off);
        if (lane >= off) v += t;
    }
    if (lane == 31) wsum[w] = v;
    __syncthreads();
    if (w == 0) {
        int sv = wsum[lane];
#pragma unroll
        for (int off = 1; off < 32; off <<= 1) {
            int t = __shfl_up_sync(0xffffffffu, sv, off);
            if (lane >= off) sv += t;
        }
        wsum[lane] = sv;
    }
    __syncthreads();
    int excl = v - local + (w > 0 ? wsum[w - 1] : 0);
    int run = excl;
    for (int i = 0; i < chunk; i++) {
        int idx = base + i;
        if (idx < N) {
            g_start[idx] = run;
            run += g_cnt[idx];
        }
    }
    if (tid == 1023) g_start[N] = run;
}

// ---------------- K3c: fill CSR ----------------
__global__ void k_fill(const int* __restrict__ ei, int E, int N) {
    int Etot = E + N;
    int stride = gridDim.x * blockDim.x;
    for (int i = blockIdx.x * blockDim.x + threadIdx.x; i < Etot; i += stride) {
        int src, dst;
        if (i < E) { src = ei[i]; dst = ei[E + i]; }
        else       { src = dst = i - E; }
        int pos = g_start[dst] + atomicAdd(&g_fill[dst], 1);
        g_csr[pos] = src;
    }
}

// ---------------- K4: per-node softmax over CSR segment (8 lanes per node) ----------------
__global__ void k_soft(int N) {
    int g = blockIdx.x * blockDim.x + threadIdx.x;
    int node = g >> 3;
    int sub = g & 7;
    bool valid = node < N;
    int nc = valid ? node : (N - 1);
    int start = g_start[nc], end = g_start[nc + 1];
    float4 ad = *(const float4*)&g_ad[nc * NHEAD];
    float4 m = make_float4(-3.4e38f, -3.4e38f, -3.4e38f, -3.4e38f);
    for (int p = start + sub; p < end; p += 8) {
        int src = g_csr[p];
        float4 as = *(const float4*)&g_as[src * NHEAD];
        m = max4(m, lrelu4(add4(as, ad)));
    }
#pragma unroll
    for (int off = 4; off >= 1; off >>= 1) {
        m.x = fmaxf(m.x, __shfl_xor_sync(0xffffffffu, m.x, off, 8));
        m.y = fmaxf(m.y, __shfl_xor_sync(0xffffffffu, m.y, off, 8));
        m.z = fmaxf(m.z, __shfl_xor_sync(0xffffffffu, m.z, off, 8));
        m.w = fmaxf(m.w, __shfl_xor_sync(0xffffffffu, m.w, off, 8));
    }
    float4 s = make_float4(0.f, 0.f, 0.f, 0.f);
    for (int p = start + sub; p < end; p += 8) {
        int src = g_csr[p];
        float4 as = *(const float4*)&g_as[src * NHEAD];
        float4 e = lrelu4(add4(as, ad));
        float4 wv = make_float4(__expf(e.x - m.x), __expf(e.y - m.y),
                                __expf(e.z - m.z), __expf(e.w - m.w));
        if (valid) *(float4*)&g_w[(size_t)p * NHEAD] = wv;
        s = add4(s, wv);
    }
#pragma unroll
    for (int off = 4; off >= 1; off >>= 1) {
        s.x += __shfl_xor_sync(0xffffffffu, s.x, off, 8);
        s.y += __shfl_xor_sync(0xffffffffu, s.y, off, 8);
        s.z += __shfl_xor_sync(0xffffffffu, s.z, off, 8);
        s.w += __shfl_xor_sync(0xffffffffu, s.w, off, 8);
    }
    if (valid && sub == 0) *(float4*)&g_s[nc * NHEAD] = s;
}

// ---------------- K5: aggregate (64 threads per node, register accum, single store) ----------------
__global__ __launch_bounds__(256) void k_agg(const float* __restrict__ bias,
                                             float* __restrict__ out, int N) {
    int node = blockIdx.x * 4 + (threadIdx.x >> 6);
    if (node >= N) return;
    int j = threadIdx.x & 63;
    int head = j >> 4;
    int start = g_start[node], end = g_start[node + 1];
    float inv_s = __frcp_rn(g_s[node * NHEAD + head]);
    float4 acc = make_float4(0.f, 0.f, 0.f, 0.f);
    for (int p = start; p < end; p++) {
        int src = __ldg(&g_csr[p]);
        float alpha = g_w[(size_t)p * NHEAD + head] * inv_s;
        float4 hv = *(const float4*)&g_h[(size_t)src * OUT_DIM + j * 4];
        acc.x += alpha * hv.x;
        acc.y += alpha * hv.y;
        acc.z += alpha * hv.z;
        acc.w += alpha * hv.w;
    }
    float4 bv = *(const float4*)&bias[j * 4];
    acc = add4(acc, bv);
    *(float4*)&out[(size_t)node * OUT_DIM + j * 4] = acc;
}

// ---------------- launch ----------------
extern "C" void kernel_launch(void* const* d_in, const int* in_sizes, int n_in,
                              void* d_out, int out_size) {
    const float* x       = (const float*)d_in[0];
    const int*   ei      = (const int*)d_in[1];
    const float* W       = (const float*)d_in[2];
    const float* att_src = (const float*)d_in[3];
    const float* att_dst = (const float*)d_in[4];
    const float* bias    = (const float*)d_in[5];
    float* out = (float*)d_out;

    int N = in_sizes[0] / IN_DIM;
    int E = in_sizes[1] / 2;
    int Etot = E + N;

    cudaFuncSetAttribute(k_gemm_mma, cudaFuncAttributeMaxDynamicSharedMemorySize, SM_GEMM_BYTES);

    k_zero<<<(2 * N + 255) / 256, 256>>>(N);
    k_wt<<<(IN_DIM * OUT_DIM + 255) / 256, 256>>>(W);
    dim3 ggrid((N + 127) / 128, OUT_DIM / 128);
    k_gemm_mma<<<ggrid, 256, SM_GEMM_BYTES>>>(x, N);
    k_att<<<(N * 32 + 255) / 256, 256>>>(att_src, att_dst, N);
    k_hist<<<(Etot + 255) / 256, 256>>>(ei, E, N);
    k_scan<<<1, 1024>>>(N);
    k_fill<<<(Etot + 255) / 256, 256>>>(ei, E, N);
    k_soft<<<(N * 8 + 255) / 256, 256>>>(N);
    k_agg<<<(N + 3) / 4, 256>>>(bias, out, N);
}

// round 6
// speedup vs baseline: 1.0385x; 1.0385x over previous
#include <cuda_runtime.h>
#include <math.h>
#include <stdint.h>

#define IN_DIM  256
#define OUT_DIM 256   // H*D = 4*64
#define NHEAD   4
#define NMAX    50000
#define EMAX    800000
#define ETOTMAX (EMAX + NMAX)

// ---------------- scratch (__device__ globals; allocation-free) ----------------
__device__ float    g_h[(size_t)NMAX * OUT_DIM];     // 51.2 MB transformed features
__device__ float    g_as[NMAX * NHEAD];
__device__ float    g_ad[NMAX * NHEAD];
__device__ int      g_cnt[NMAX];
__device__ int      g_fill[NMAX];
__device__ int      g_start[NMAX + 1];
__device__ int      g_csr[ETOTMAX];
__device__ float    g_w[(size_t)ETOTMAX * NHEAD];
__device__ float    g_s[NMAX * NHEAD];
__device__ unsigned g_wh[IN_DIM * OUT_DIM];          // W hi (tf32 bits), [k][n]
__device__ unsigned g_wl[IN_DIM * OUT_DIM];          // W lo residual (tf32 bits), [k][n]

__device__ __forceinline__ unsigned tf32_bits(float f) {
    unsigned r; asm("cvt.rna.tf32.f32 %0, %1;" : "=r"(r) : "f"(f)); return r;
}

__device__ __forceinline__ void mma_tf32(float* c, uint32_t a0, uint32_t a1,
                                         uint32_t a2, uint32_t a3,
                                         uint32_t b0, uint32_t b1) {
    asm("mma.sync.aligned.m16n8k8.row.col.f32.tf32.tf32.f32 "
        "{%0,%1,%2,%3},{%4,%5,%6,%7},{%8,%9},{%0,%1,%2,%3};"
        : "+f"(c[0]), "+f"(c[1]), "+f"(c[2]), "+f"(c[3])
        : "r"(a0), "r"(a1), "r"(a2), "r"(a3), "r"(b0), "r"(b1));
}

__device__ __forceinline__ void cp_async16(unsigned* smem_ptr, const void* gptr) {
    uint32_t s = (uint32_t)__cvta_generic_to_shared(smem_ptr);
    asm volatile("cp.async.cg.shared.global [%0], [%1], 16;" :: "r"(s), "l"(gptr) : "memory");
}
#define CP_COMMIT() asm volatile("cp.async.commit_group;" ::: "memory")
#define CP_WAIT0()  asm volatile("cp.async.wait_group 0;" ::: "memory")

__device__ __forceinline__ float lrelu(float x) { return x > 0.f ? x : 0.2f * x; }
__device__ __forceinline__ float4 lrelu4(float4 a) {
    return make_float4(lrelu(a.x), lrelu(a.y), lrelu(a.z), lrelu(a.w));
}
__device__ __forceinline__ float4 add4(float4 a, float4 b) {
    return make_float4(a.x + b.x, a.y + b.y, a.z + b.z, a.w + b.w);
}
__device__ __forceinline__ float4 max4(float4 a, float4 b) {
    return make_float4(fmaxf(a.x, b.x), fmaxf(a.y, b.y), fmaxf(a.z, b.z), fmaxf(a.w, b.w));
}

// ---------------- K0: zero counters ----------------
__global__ void k_zero(int N) {
    int stride = gridDim.x * blockDim.x;
    for (int i = blockIdx.x * blockDim.x + threadIdx.x; i < 2 * N; i += stride) {
        if (i < N) g_cnt[i] = 0; else g_fill[i - N] = 0;
    }
}

// ---------------- K0b: W -> tf32 hi/lo split, [k][n] layout kept ----------------
__global__ void k_wt(const float* __restrict__ W) {
    int idx = blockIdx.x * blockDim.x + threadIdx.x;
    if (idx >= IN_DIM * OUT_DIM) return;
    float w = W[idx];
    unsigned hi = tf32_bits(w);
    unsigned lo = tf32_bits(w - __uint_as_float(hi));
    g_wh[idx] = hi;
    g_wl[idx] = lo;
}

// ---------------- K1: GEMM h = x @ W via mma.sync tf32, 2-pass W split, pipelined ----------------
// BM=128, BN=128, BK=32; 8 warps, warp tile 32x64. Double-buffered smem.
#define XS_STRIDE 36
#define WS_STRIDE 136
#define XS_BUF (128 * XS_STRIDE)     // 4608
#define WS_BUF (32 * WS_STRIDE)      // 4352
#define OFF_XS 0
#define OFF_WH (2 * XS_BUF)                        // 9216
#define OFF_WL (OFF_WH + 2 * WS_BUF)               // 17920
#define SM_GEMM_WORDS (OFF_WL + 2 * WS_BUF)        // 26624 words
#define SM_GEMM_BYTES (SM_GEMM_WORDS * 4)          // 106496 B
__global__ __launch_bounds__(256) void k_gemm_mma(const float* __restrict__ x, int N) {
    extern __shared__ unsigned smem[];
    int tid = threadIdx.x;
    int wid = tid >> 5, lane = tid & 31;
    int g = lane >> 2, t = lane & 3;
    int m0 = blockIdx.x * 128;
    int n0 = blockIdx.y * 128;
    int wm = (wid & 3) * 32;
    int wn = (wid >> 2) * 64;

    float acc[2][8][4];
#pragma unroll
    for (int mt = 0; mt < 2; mt++)
#pragma unroll
        for (int nt = 0; nt < 8; nt++)
#pragma unroll
            for (int i = 0; i < 4; i++) acc[mt][nt][i] = 0.f;

    int xrow = tid >> 1;                 // 0..127
    int xkq  = (tid & 1) * 16;           // 0 or 16
    int wrow = tid >> 3;                 // 0..31
    int wcq  = (tid & 7) * 16;           // 0..112
    int grow = m0 + xrow;
    bool xok = grow < N;
    const float* xbase = &x[(size_t)grow * IN_DIM + xkq];

    // prologue: issue W[0] cp.async, prefetch x[0] to regs
    {
        const unsigned* whp = &g_wh[(size_t)wrow * OUT_DIM + n0 + wcq];
        const unsigned* wlp = &g_wl[(size_t)wrow * OUT_DIM + n0 + wcq];
#pragma unroll
        for (int i = 0; i < 4; i++) {
            cp_async16(&smem[OFF_WH + wrow * WS_STRIDE + wcq + i * 4], whp + i * 4);
            cp_async16(&smem[OFF_WL + wrow * WS_STRIDE + wcq + i * 4], wlp + i * 4);
        }
        CP_COMMIT();
    }
    float4 xv[4];
#pragma unroll
    for (int i = 0; i < 4; i++)
        xv[i] = xok ? *(const float4*)(xbase + i * 4) : make_float4(0.f, 0.f, 0.f, 0.f);

    for (int kt = 0; kt < 8; kt++) {
        int cur = kt & 1;
        unsigned* xsc = smem + OFF_XS + cur * XS_BUF;
        // convert + store x tile
#pragma unroll
        for (int i = 0; i < 4; i++) {
            uint4 b = make_uint4(tf32_bits(xv[i].x), tf32_bits(xv[i].y),
                                 tf32_bits(xv[i].z), tf32_bits(xv[i].w));
            *(uint4*)&xsc[xrow * XS_STRIDE + xkq + i * 4] = b;
        }
        CP_WAIT0();
        __syncthreads();

        if (kt < 7) {
            int nb = 1 - cur;
            int k1 = (kt + 1) * 32;
            const unsigned* whp = &g_wh[(size_t)(k1 + wrow) * OUT_DIM + n0 + wcq];
            const unsigned* wlp = &g_wl[(size_t)(k1 + wrow) * OUT_DIM + n0 + wcq];
#pragma unroll
            for (int i = 0; i < 4; i++) {
                cp_async16(&smem[OFF_WH + nb * WS_BUF + wrow * WS_STRIDE + wcq + i * 4], whp + i * 4);
                cp_async16(&smem[OFF_WL + nb * WS_BUF + wrow * WS_STRIDE + wcq + i * 4], wlp + i * 4);
            }
            CP_COMMIT();
            const float* xn = xbase + k1;
#pragma unroll
            for (int i = 0; i < 4; i++)
                xv[i] = xok ? *(const float4*)(xn + i * 4) : make_float4(0.f, 0.f, 0.f, 0.f);
        }

        unsigned* whc = smem + OFF_WH + cur * WS_BUF;
        unsigned* wlc = smem + OFF_WL + cur * WS_BUF;
#pragma unroll
        for (int kk = 0; kk < 32; kk += 8) {
            uint32_t a[2][4];
#pragma unroll
            for (int mt = 0; mt < 2; mt++) {
                int rbase = (wm + mt * 16 + g) * XS_STRIDE + kk;
                a[mt][0] = xsc[rbase + t];
                a[mt][1] = xsc[rbase + 8 * XS_STRIDE + t];
                a[mt][2] = xsc[rbase + t + 4];
                a[mt][3] = xsc[rbase + 8 * XS_STRIDE + t + 4];
            }
#pragma unroll
            for (int nt = 0; nt < 8; nt++) {
                int cb = (kk + t) * WS_STRIDE + wn + nt * 8 + g;
                uint32_t bh0 = whc[cb], bh1 = whc[cb + 4 * WS_STRIDE];
                uint32_t bl0 = wlc[cb], bl1 = wlc[cb + 4 * WS_STRIDE];
#pragma unroll
                for (int mt = 0; mt < 2; mt++) {
                    mma_tf32(acc[mt][nt], a[mt][0], a[mt][1], a[mt][2], a[mt][3], bh0, bh1);
                    mma_tf32(acc[mt][nt], a[mt][0], a[mt][1], a[mt][2], a[mt][3], bl0, bl1);
                }
            }
        }
        __syncthreads();
    }

    // store: acc[mt][nt][0..3] -> rows (g, g+8) of m-tile, cols 2t,2t+1 of n-tile
#pragma unroll
    for (int mt = 0; mt < 2; mt++) {
        int r0 = m0 + wm + mt * 16 + g;
        int r1 = r0 + 8;
#pragma unroll
        for (int nt = 0; nt < 8; nt++) {
            int c = n0 + wn + nt * 8 + 2 * t;
            if (r0 < N) *(float2*)&g_h[(size_t)r0 * OUT_DIM + c] =
                make_float2(acc[mt][nt][0], acc[mt][nt][1]);
            if (r1 < N) *(float2*)&g_h[(size_t)r1 * OUT_DIM + c] =
                make_float2(acc[mt][nt][2], acc[mt][nt][3]);
        }
    }
}

// ---------------- K2: per-node attention logits (one warp per node) ----------------
__global__ void k_att(const float* __restrict__ att_src, const float* __restrict__ att_dst, int N) {
    int warp = (blockIdx.x * blockDim.x + threadIdx.x) >> 5;
    int lane = threadIdx.x & 31;
    if (warp >= N) return;
    const float* hp = &g_h[(size_t)warp * OUT_DIM + lane * 8];
    float4 a0 = *(const float4*)hp;
    float4 a1 = *(const float4*)(hp + 4);
    float4 s0 = *(const float4*)&att_src[lane * 8];
    float4 s1 = *(const float4*)&att_src[lane * 8 + 4];
    float4 d0 = *(const float4*)&att_dst[lane * 8];
    float4 d1 = *(const float4*)&att_dst[lane * 8 + 4];
    float ss = a0.x*s0.x + a0.y*s0.y + a0.z*s0.z + a0.w*s0.w
             + a1.x*s1.x + a1.y*s1.y + a1.z*s1.z + a1.w*s1.w;
    float sd = a0.x*d0.x + a0.y*d0.y + a0.z*d0.z + a0.w*d0.w
             + a1.x*d1.x + a1.y*d1.y + a1.z*d1.z + a1.w*d1.w;
#pragma unroll
    for (int off = 4; off >= 1; off >>= 1) {
        ss += __shfl_down_sync(0xffffffffu, ss, off, 8);
        sd += __shfl_down_sync(0xffffffffu, sd, off, 8);
    }
    if ((lane & 7) == 0) {
        int head = lane >> 3;
        g_as[warp * NHEAD + head] = ss;
        g_ad[warp * NHEAD + head] = sd;
    }
}

// ---------------- K3a: histogram of dst ----------------
__global__ void k_hist(const int* __restrict__ ei, int E, int N) {
    int Etot = E + N;
    int stride = gridDim.x * blockDim.x;
    for (int i = blockIdx.x * blockDim.x + threadIdx.x; i < Etot; i += stride) {
        int dst = (i < E) ? ei[E + i] : (i - E);
        atomicAdd(&g_cnt[dst], 1);
    }
}

// ---------------- K3b: exclusive scan (single block) ----------------
__global__ __launch_bounds__(1024) void k_scan(int N) {
    __shared__ int wsum[32];
    int tid = threadIdx.x;
    int chunk = (N + 1023) >> 10;
    int base = tid * chunk;
    int local = 0;
    for (int i = 0; i < chunk; i++) {
        int idx = base + i;
        if (idx < N) local += g_cnt[idx];
    }
    int lane = tid & 31, w = tid >> 5;
    int v = local;
#pragma unroll
    for (int off = 1; off < 32; off <<= 1) {
        int t = __shfl_up_sync(0xffffffffu, v, off);
        if (lane >= off) v += t;
    }
    if (lane == 31) wsum[w] = v;
    __syncthreads();
    if (w == 0) {
        int sv = wsum[lane];
#pragma unroll
        for (int off = 1; off < 32; off <<= 1) {
            int t = __shfl_up_sync(0xffffffffu, sv, off);
            if (lane >= off) sv += t;
        }
        wsum[lane] = sv;
    }
    __syncthreads();
    int excl = v - local + (w > 0 ? wsum[w - 1] : 0);
    int run = excl;
    for (int i = 0; i < chunk; i++) {
        int idx = base + i;
        if (idx < N) {
            g_start[idx] = run;
            run += g_cnt[idx];
        }
    }
    if (tid == 1023) g_start[N] = run;
}

// ---------------- K3c: fill CSR ----------------
__global__ void k_fill(const int* __restrict__ ei, int E, int N) {
    int Etot = E + N;
    int stride = gridDim.x * blockDim.x;
    for (int i = blockIdx.x * blockDim.x + threadIdx.x; i < Etot; i += stride) {
        int src, dst;
        if (i < E) { src = ei[i]; dst = ei[E + i]; }
        else       { src = dst = i - E; }
        int pos = g_start[dst] + atomicAdd(&g_fill[dst], 1);
        g_csr[pos] = src;
    }
}

// ---------------- K4: per-node softmax over CSR segment (8 lanes per node) ----------------
__global__ void k_soft(int N) {
    int g = blockIdx.x * blockDim.x + threadIdx.x;
    int node = g >> 3;
    int sub = g & 7;
    bool valid = node < N;
    int nc = valid ? node : (N - 1);
    int start = g_start[nc], end = g_start[nc + 1];
    float4 ad = *(const float4*)&g_ad[nc * NHEAD];
    float4 m = make_float4(-3.4e38f, -3.4e38f, -3.4e38f, -3.4e38f);
    for (int p = start + sub; p < end; p += 8) {
        int src = g_csr[p];
        float4 as = *(const float4*)&g_as[src * NHEAD];
        m = max4(m, lrelu4(add4(as, ad)));
    }
#pragma unroll
    for (int off = 4; off >= 1; off >>= 1) {
        m.x = fmaxf(m.x, __shfl_xor_sync(0xffffffffu, m.x, off, 8));
        m.y = fmaxf(m.y, __shfl_xor_sync(0xffffffffu, m.y, off, 8));
        m.z = fmaxf(m.z, __shfl_xor_sync(0xffffffffu, m.z, off, 8));
        m.w = fmaxf(m.w, __shfl_xor_sync(0xffffffffu, m.w, off, 8));
    }
    float4 s = make_float4(0.f, 0.f, 0.f, 0.f);
    for (int p = start + sub; p < end; p += 8) {
        int src = g_csr[p];
        float4 as = *(const float4*)&g_as[src * NHEAD];
        float4 e = lrelu4(add4(as, ad));
        float4 wv = make_float4(__expf(e.x - m.x), __expf(e.y - m.y),
                                __expf(e.z - m.z), __expf(e.w - m.w));
        if (valid) *(float4*)&g_w[(size_t)p * NHEAD] = wv;
        s = add4(s, wv);
    }
#pragma unroll
    for (int off = 4; off >= 1; off >>= 1) {
        s.x += __shfl_xor_sync(0xffffffffu, s.x, off, 8);
        s.y += __shfl_xor_sync(0xffffffffu, s.y, off, 8);
        s.z += __shfl_xor_sync(0xffffffffu, s.z, off, 8);
        s.w += __shfl_xor_sync(0xffffffffu, s.w, off, 8);
    }
    if (valid && sub == 0) *(float4*)&g_s[nc * NHEAD] = s;
}

// ---------------- K5: aggregate (64 threads per node, register accum, single store) ----------------
__global__ __launch_bounds__(256) void k_agg(const float* __restrict__ bias,
                                             float* __restrict__ out, int N) {
    int node = blockIdx.x * 4 + (threadIdx.x >> 6);
    if (node >= N) return;
    int j = threadIdx.x & 63;
    int head = j >> 4;
    int start = g_start[node], end = g_start[node + 1];
    float inv_s = __frcp_rn(g_s[node * NHEAD + head]);
    float4 acc = make_float4(0.f, 0.f, 0.f, 0.f);
    for (int p = start; p < end; p++) {
        int src = __ldg(&g_csr[p]);
        float alpha = g_w[(size_t)p * NHEAD + head] * inv_s;
        float4 hv = *(const float4*)&g_h[(size_t)src * OUT_DIM + j * 4];
        acc.x += alpha * hv.x;
        acc.y += alpha * hv.y;
        acc.z += alpha * hv.z;
        acc.w += alpha * hv.w;
    }
    float4 bv = *(const float4*)&bias[j * 4];
    acc = add4(acc, bv);
    *(float4*)&out[(size_t)node * OUT_DIM + j * 4] = acc;
}

// ---------------- launch ----------------
extern "C" void kernel_launch(void* const* d_in, const int* in_sizes, int n_in,
                              void* d_out, int out_size) {
    const float* x       = (const float*)d_in[0];
    const int*   ei      = (const int*)d_in[1];
    const float* W       = (const float*)d_in[2];
    const float* att_src = (const float*)d_in[3];
    const float* att_dst = (const float*)d_in[4];
    const float* bias    = (const float*)d_in[5];
    float* out = (float*)d_out;

    int N = in_sizes[0] / IN_DIM;
    int E = in_sizes[1] / 2;
    int Etot = E + N;

    cudaFuncSetAttribute(k_gemm_mma, cudaFuncAttributeMaxDynamicSharedMemorySize, SM_GEMM_BYTES);

    k_zero<<<(2 * N + 255) / 256, 256>>>(N);
    k_wt<<<(IN_DIM * OUT_DIM + 255) / 256, 256>>>(W);
    k_hist<<<(Etot + 255) / 256, 256>>>(ei, E, N);
    dim3 ggrid((N + 127) / 128, OUT_DIM / 128);
    k_gemm_mma<<<ggrid, 256, SM_GEMM_BYTES>>>(x, N);   // launch #4 -> ncu captures this
    k_att<<<(N * 32 + 255) / 256, 256>>>(att_src, att_dst, N);
    k_scan<<<1, 1024>>>(N);
    k_fill<<<(Etot + 255) / 256, 256>>>(ei, E, N);
    k_soft<<<(N * 8 + 255) / 256, 256>>>(N);
    k_agg<<<(N + 3) / 4, 256>>>(bias, out, N);
}

// round 7
// speedup vs baseline: 1.1592x; 1.1161x over previous
#include <cuda_runtime.h>
#include <math.h>
#include <stdint.h>

#define IN_DIM  256
#define OUT_DIM 256   // H*D = 4*64
#define NHEAD   4
#define NMAX    50000
#define EMAX    800000
#define ETOTMAX (EMAX + NMAX)

// ---------------- scratch (__device__ globals; allocation-free) ----------------
__device__ float    g_h[(size_t)NMAX * OUT_DIM];     // 51.2 MB transformed features
__device__ float    g_as[NMAX * NHEAD];
__device__ float    g_ad[NMAX * NHEAD];
__device__ int      g_cnt[NMAX];
__device__ int      g_fill[NMAX];
__device__ int      g_start[NMAX + 1];
__device__ int      g_csr[ETOTMAX];
__device__ float    g_w[(size_t)ETOTMAX * NHEAD];
__device__ float    g_s[NMAX * NHEAD];
__device__ unsigned g_wh[IN_DIM * OUT_DIM];          // W hi (tf32 bits), [k][n]
__device__ unsigned g_wl[IN_DIM * OUT_DIM];          // W lo residual (tf32 bits), [k][n]

__device__ __forceinline__ unsigned tf32_bits(float f) {
    unsigned r; asm("cvt.rna.tf32.f32 %0, %1;" : "=r"(r) : "f"(f)); return r;
}

__device__ __forceinline__ void mma_tf32(float* c, uint32_t a0, uint32_t a1,
                                         uint32_t a2, uint32_t a3,
                                         uint32_t b0, uint32_t b1) {
    asm("mma.sync.aligned.m16n8k8.row.col.f32.tf32.tf32.f32 "
        "{%0,%1,%2,%3},{%4,%5,%6,%7},{%8,%9},{%0,%1,%2,%3};"
        : "+f"(c[0]), "+f"(c[1]), "+f"(c[2]), "+f"(c[3])
        : "r"(a0), "r"(a1), "r"(a2), "r"(a3), "r"(b0), "r"(b1));
}

__device__ __forceinline__ void cp_async16(unsigned* smem_ptr, const void* gptr) {
    uint32_t s = (uint32_t)__cvta_generic_to_shared(smem_ptr);
    asm volatile("cp.async.cg.shared.global [%0], [%1], 16;" :: "r"(s), "l"(gptr) : "memory");
}
#define CP_COMMIT() asm volatile("cp.async.commit_group;" ::: "memory")
#define CP_WAIT0()  asm volatile("cp.async.wait_group 0;" ::: "memory")

__device__ __forceinline__ float lrelu(float x) { return x > 0.f ? x : 0.2f * x; }
__device__ __forceinline__ float4 lrelu4(float4 a) {
    return make_float4(lrelu(a.x), lrelu(a.y), lrelu(a.z), lrelu(a.w));
}
__device__ __forceinline__ float4 add4(float4 a, float4 b) {
    return make_float4(a.x + b.x, a.y + b.y, a.z + b.z, a.w + b.w);
}
__device__ __forceinline__ float4 max4(float4 a, float4 b) {
    return make_float4(fmaxf(a.x, b.x), fmaxf(a.y, b.y), fmaxf(a.z, b.z), fmaxf(a.w, b.w));
}

// ---------------- K0: zero counters + logits accumulators ----------------
__global__ void k_zero(int N) {
    int stride = gridDim.x * blockDim.x;
    int gid = blockIdx.x * blockDim.x + threadIdx.x;
    for (int i = gid; i < 2 * N; i += stride) {
        if (i < N) g_cnt[i] = 0; else g_fill[i - N] = 0;
    }
    for (int i = gid; i < 4 * N; i += stride) { g_as[i] = 0.f; g_ad[i] = 0.f; }
}

// ---------------- K0b: W -> tf32 hi/lo split, [k][n] layout kept ----------------
__global__ void k_wt(const float* __restrict__ W) {
    int idx = blockIdx.x * blockDim.x + threadIdx.x;
    if (idx >= IN_DIM * OUT_DIM) return;
    float w = W[idx];
    unsigned hi = tf32_bits(w);
    unsigned lo = tf32_bits(w - __uint_as_float(hi));
    g_wh[idx] = hi;
    g_wl[idx] = lo;
}

// ---------------- K3a: histogram of dst ----------------
__global__ void k_hist(const int* __restrict__ ei, int E, int N) {
    int Etot = E + N;
    int stride = gridDim.x * blockDim.x;
    for (int i = blockIdx.x * blockDim.x + threadIdx.x; i < Etot; i += stride) {
        int dst = (i < E) ? ei[E + i] : (i - E);
        atomicAdd(&g_cnt[dst], 1);
    }
}

// ---------------- K1: GEMM h = x @ W (mma.sync tf32 2-pass) + fused att logits ----------------
// BM=128, BN=128, BK=32; 16 warps (512 thr), warp tile 32x32.
// x tile single-buffered (reg-prefetched), W hi/lo double-buffered via cp.async.
#define XS_STRIDE 36
#define WS_STRIDE 136
#define XS_BUF (128 * XS_STRIDE)     // 4608 words
#define WS_BUF (32 * WS_STRIDE)      // 4352 words
#define OFF_XS 0
#define OFF_WH XS_BUF                              // 4608
#define OFF_WL (OFF_WH + 2 * WS_BUF)               // 13312
#define SM_GEMM_WORDS (OFF_WL + 2 * WS_BUF)        // 22016 words
#define SM_GEMM_BYTES (SM_GEMM_WORDS * 4)          // 88064 B
__global__ __launch_bounds__(512) void k_gemm_mma(const float* __restrict__ x,
                                                  const float* __restrict__ att_src,
                                                  const float* __restrict__ att_dst, int N) {
    extern __shared__ unsigned smem[];
    unsigned* xs = smem + OFF_XS;
    int tid = threadIdx.x;
    int wid = tid >> 5, lane = tid & 31;
    int g = lane >> 2, t = lane & 3;
    int m0 = blockIdx.x * 128;
    int n0 = blockIdx.y * 128;
    int wm = (wid & 3) * 32;        // warp row offset
    int wn = (wid >> 2) * 32;       // warp col offset (4 warps along N)

    float acc[2][4][4];
#pragma unroll
    for (int mt = 0; mt < 2; mt++)
#pragma unroll
        for (int nt = 0; nt < 4; nt++)
#pragma unroll
            for (int i = 0; i < 4; i++) acc[mt][nt][i] = 0.f;

    int xrow = tid >> 2;                 // 0..127
    int xkq  = (tid & 3) * 8;            // 0,8,16,24
    int wrow = tid >> 4;                 // 0..31
    int wcq  = (tid & 15) * 8;           // 0..120
    int grow = m0 + xrow;
    bool xok = grow < N;
    const float* xbase = &x[(size_t)grow * IN_DIM + xkq];

    // prologue: issue W[0] cp.async, prefetch x[0] to regs
    {
        const unsigned* whp = &g_wh[(size_t)wrow * OUT_DIM + n0 + wcq];
        const unsigned* wlp = &g_wl[(size_t)wrow * OUT_DIM + n0 + wcq];
#pragma unroll
        for (int i = 0; i < 2; i++) {
            cp_async16(&smem[OFF_WH + wrow * WS_STRIDE + wcq + i * 4], whp + i * 4);
            cp_async16(&smem[OFF_WL + wrow * WS_STRIDE + wcq + i * 4], wlp + i * 4);
        }
        CP_COMMIT();
    }
    float4 xv[2];
#pragma unroll
    for (int i = 0; i < 2; i++)
        xv[i] = xok ? *(const float4*)(xbase + i * 4) : make_float4(0.f, 0.f, 0.f, 0.f);

    for (int kt = 0; kt < 8; kt++) {
        int cur = kt & 1;
        // convert + store x tile (single buffer; prior compute fenced by loop-end barrier)
#pragma unroll
        for (int i = 0; i < 2; i++) {
            uint4 b = make_uint4(tf32_bits(xv[i].x), tf32_bits(xv[i].y),
                                 tf32_bits(xv[i].z), tf32_bits(xv[i].w));
            *(uint4*)&xs[xrow * XS_STRIDE + xkq + i * 4] = b;
        }
        CP_WAIT0();
        __syncthreads();

        if (kt < 7) {
            int nb = 1 - cur;
            int k1 = (kt + 1) * 32;
            const unsigned* whp = &g_wh[(size_t)(k1 + wrow) * OUT_DIM + n0 + wcq];
            const unsigned* wlp = &g_wl[(size_t)(k1 + wrow) * OUT_DIM + n0 + wcq];
#pragma unroll
            for (int i = 0; i < 2; i++) {
                cp_async16(&smem[OFF_WH + nb * WS_BUF + wrow * WS_STRIDE + wcq + i * 4], whp + i * 4);
                cp_async16(&smem[OFF_WL + nb * WS_BUF + wrow * WS_STRIDE + wcq + i * 4], wlp + i * 4);
            }
            CP_COMMIT();
            const float* xn = xbase + k1;
#pragma unroll
            for (int i = 0; i < 2; i++)
                xv[i] = xok ? *(const float4*)(xn + i * 4) : make_float4(0.f, 0.f, 0.f, 0.f);
        }

        unsigned* whc = smem + OFF_WH + cur * WS_BUF;
        unsigned* wlc = smem + OFF_WL + cur * WS_BUF;
#pragma unroll
        for (int kk = 0; kk < 32; kk += 8) {
            uint32_t a[2][4];
#pragma unroll
            for (int mt = 0; mt < 2; mt++) {
                int rbase = (wm + mt * 16 + g) * XS_STRIDE + kk;
                a[mt][0] = xs[rbase + t];
                a[mt][1] = xs[rbase + 8 * XS_STRIDE + t];
                a[mt][2] = xs[rbase + t + 4];
                a[mt][3] = xs[rbase + 8 * XS_STRIDE + t + 4];
            }
            uint32_t bh[4][2], bl[4][2];
#pragma unroll
            for (int nt = 0; nt < 4; nt++) {
                int cb = (kk + t) * WS_STRIDE + wn + nt * 8 + g;
                bh[nt][0] = whc[cb]; bh[nt][1] = whc[cb + 4 * WS_STRIDE];
                bl[nt][0] = wlc[cb]; bl[nt][1] = wlc[cb + 4 * WS_STRIDE];
            }
            // hi pass then lo pass: 16 independent accumulators, no back-to-back RAW
#pragma unroll
            for (int nt = 0; nt < 4; nt++) {
                mma_tf32(acc[0][nt], a[0][0], a[0][1], a[0][2], a[0][3], bh[nt][0], bh[nt][1]);
                mma_tf32(acc[1][nt], a[1][0], a[1][1], a[1][2], a[1][3], bh[nt][0], bh[nt][1]);
            }
#pragma unroll
            for (int nt = 0; nt < 4; nt++) {
                mma_tf32(acc[0][nt], a[0][0], a[0][1], a[0][2], a[0][3], bl[nt][0], bl[nt][1]);
                mma_tf32(acc[1][nt], a[1][0], a[1][1], a[1][2], a[1][3], bl[nt][0], bl[nt][1]);
            }
        }
        __syncthreads();
    }

    // epilogue: store h + fused attention-logit partials
    int head = (n0 + wn) >> 6;   // 32-col warp block never straddles a 64-wide head
#pragma unroll
    for (int mt = 0; mt < 2; mt++) {
        int r0 = m0 + wm + mt * 16 + g;
        int r1 = r0 + 8;
        float s0 = 0.f, d0 = 0.f, s1 = 0.f, d1 = 0.f;
#pragma unroll
        for (int nt = 0; nt < 4; nt++) {
            int c = n0 + wn + nt * 8 + 2 * t;
            if (r0 < N) *(float2*)&g_h[(size_t)r0 * OUT_DIM + c] =
                make_float2(acc[mt][nt][0], acc[mt][nt][1]);
            if (r1 < N) *(float2*)&g_h[(size_t)r1 * OUT_DIM + c] =
                make_float2(acc[mt][nt][2], acc[mt][nt][3]);
            float as0 = __ldg(&att_src[c]), as1 = __ldg(&att_src[c + 1]);
            float ad0 = __ldg(&att_dst[c]), ad1 = __ldg(&att_dst[c + 1]);
            s0 += acc[mt][nt][0] * as0 + acc[mt][nt][1] * as1;
            d0 += acc[mt][nt][0] * ad0 + acc[mt][nt][1] * ad1;
            s1 += acc[mt][nt][2] * as0 + acc[mt][nt][3] * as1;
            d1 += acc[mt][nt][2] * ad0 + acc[mt][nt][3] * ad1;
        }
#pragma unroll
        for (int off = 2; off >= 1; off >>= 1) {
            s0 += __shfl_down_sync(0xffffffffu, s0, off, 4);
            d0 += __shfl_down_sync(0xffffffffu, d0, off, 4);
            s1 += __shfl_down_sync(0xffffffffu, s1, off, 4);
            d1 += __shfl_down_sync(0xffffffffu, d1, off, 4);
        }
        if (t == 0) {
            if (r0 < N) {
                atomicAdd(&g_as[r0 * NHEAD + head], s0);
                atomicAdd(&g_ad[r0 * NHEAD + head], d0);
            }
            if (r1 < N) {
                atomicAdd(&g_as[r1 * NHEAD + head], s1);
                atomicAdd(&g_ad[r1 * NHEAD + head], d1);
            }
        }
    }
}

// ---------------- K3b: exclusive scan (single block) ----------------
__global__ __launch_bounds__(1024) void k_scan(int N) {
    __shared__ int wsum[32];
    int tid = threadIdx.x;
    int chunk = (N + 1023) >> 10;
    int base = tid * chunk;
    int local = 0;
    for (int i = 0; i < chunk; i++) {
        int idx = base + i;
        if (idx < N) local += g_cnt[idx];
    }
    int lane = tid & 31, w = tid >> 5;
    int v = local;
#pragma unroll
    for (int off = 1; off < 32; off <<= 1) {
        int t = __shfl_up_sync(0xffffffffu, v, off);
        if (lane >= off) v += t;
    }
    if (lane == 31) wsum[w] = v;
    __syncthreads();
    if (w == 0) {
        int sv = wsum[lane];
#pragma unroll
        for (int off = 1; off < 32; off <<= 1) {
            int t = __shfl_up_sync(0xffffffffu, sv, off);
            if (lane >= off) sv += t;
        }
        wsum[lane] = sv;
    }
    __syncthreads();
    int excl = v - local + (w > 0 ? wsum[w - 1] : 0);
    int run = excl;
    for (int i = 0; i < chunk; i++) {
        int idx = base + i;
        if (idx < N) {
            g_start[idx] = run;
            run += g_cnt[idx];
        }
    }
    if (tid == 1023) g_start[N] = run;
}

// ---------------- K3c: fill CSR ----------------
__global__ void k_fill(const int* __restrict__ ei, int E, int N) {
    int Etot = E + N;
    int stride = gridDim.x * blockDim.x;
    for (int i = blockIdx.x * blockDim.x + threadIdx.x; i < Etot; i += stride) {
        int src, dst;
        if (i < E) { src = ei[i]; dst = ei[E + i]; }
        else       { src = dst = i - E; }
        int pos = g_start[dst] + atomicAdd(&g_fill[dst], 1);
        g_csr[pos] = src;
    }
}

// ---------------- K4: per-node softmax over CSR segment (8 lanes per node) ----------------
__global__ void k_soft(int N) {
    int g = blockIdx.x * blockDim.x + threadIdx.x;
    int node = g >> 3;
    int sub = g & 7;
    bool valid = node < N;
    int nc = valid ? node : (N - 1);
    int start = g_start[nc], end = g_start[nc + 1];
    float4 ad = *(const float4*)&g_ad[nc * NHEAD];
    float4 m = make_float4(-3.4e38f, -3.4e38f, -3.4e38f, -3.4e38f);
    for (int p = start + sub; p < end; p += 8) {
        int src = g_csr[p];
        float4 as = *(const float4*)&g_as[src * NHEAD];
        m = max4(m, lrelu4(add4(as, ad)));
    }
#pragma unroll
    for (int off = 4; off >= 1; off >>= 1) {
        m.x = fmaxf(m.x, __shfl_xor_sync(0xffffffffu, m.x, off, 8));
        m.y = fmaxf(m.y, __shfl_xor_sync(0xffffffffu, m.y, off, 8));
        m.z = fmaxf(m.z, __shfl_xor_sync(0xffffffffu, m.z, off, 8));
        m.w = fmaxf(m.w, __shfl_xor_sync(0xffffffffu, m.w, off, 8));
    }
    float4 s = make_float4(0.f, 0.f, 0.f, 0.f);
    for (int p = start + sub; p < end; p += 8) {
        int src = g_csr[p];
        float4 as = *(const float4*)&g_as[src * NHEAD];
        float4 e = lrelu4(add4(as, ad));
        float4 wv = make_float4(__expf(e.x - m.x), __expf(e.y - m.y),
                                __expf(e.z - m.z), __expf(e.w - m.w));
        if (valid) *(float4*)&g_w[(size_t)p * NHEAD] = wv;
        s = add4(s, wv);
    }
#pragma unroll
    for (int off = 4; off >= 1; off >>= 1) {
        s.x += __shfl_xor_sync(0xffffffffu, s.x, off, 8);
        s.y += __shfl_xor_sync(0xffffffffu, s.y, off, 8);
        s.z += __shfl_xor_sync(0xffffffffu, s.z, off, 8);
        s.w += __shfl_xor_sync(0xffffffffu, s.w, off, 8);
    }
    if (valid && sub == 0) *(float4*)&g_s[nc * NHEAD] = s;
}

// ---------------- K5: aggregate (64 threads per node, register accum, single store) ----------------
__global__ __launch_bounds__(256) void k_agg(const float* __restrict__ bias,
                                             float* __restrict__ out, int N) {
    int node = blockIdx.x * 4 + (threadIdx.x >> 6);
    if (node >= N) return;
    int j = threadIdx.x & 63;
    int head = j >> 4;
    int start = g_start[node], end = g_start[node + 1];
    float inv_s = __frcp_rn(g_s[node * NHEAD + head]);
    float4 acc = make_float4(0.f, 0.f, 0.f, 0.f);
    for (int p = start; p < end; p++) {
        int src = __ldg(&g_csr[p]);
        float alpha = g_w[(size_t)p * NHEAD + head] * inv_s;
        float4 hv = *(const float4*)&g_h[(size_t)src * OUT_DIM + j * 4];
        acc.x += alpha * hv.x;
        acc.y += alpha * hv.y;
        acc.z += alpha * hv.z;
        acc.w += alpha * hv.w;
    }
    float4 bv = *(const float4*)&bias[j * 4];
    acc = add4(acc, bv);
    *(float4*)&out[(size_t)node * OUT_DIM + j * 4] = acc;
}

// ---------------- launch ----------------
extern "C" void kernel_launch(void* const* d_in, const int* in_sizes, int n_in,
                              void* d_out, int out_size) {
    const float* x       = (const float*)d_in[0];
    const int*   ei      = (const int*)d_in[1];
    const float* W       = (const float*)d_in[2];
    const float* att_src = (const float*)d_in[3];
    const float* att_dst = (const float*)d_in[4];
    const float* bias    = (const float*)d_in[5];
    float* out = (float*)d_out;

    int N = in_sizes[0] / IN_DIM;
    int E = in_sizes[1] / 2;
    int Etot = E + N;

    cudaFuncSetAttribute(k_gemm_mma, cudaFuncAttributeMaxDynamicSharedMemorySize, SM_GEMM_BYTES);

    k_zero<<<(4 * N + 255) / 256, 256>>>(N);
    k_wt<<<(IN_DIM * OUT_DIM + 255) / 256, 256>>>(W);
    k_hist<<<(Etot + 255) / 256, 256>>>(ei, E, N);
    dim3 ggrid((N + 127) / 128, OUT_DIM / 128);
    k_gemm_mma<<<ggrid, 512, SM_GEMM_BYTES>>>(x, att_src, att_dst, N);  // launch #4 for ncu
    k_scan<<<1, 1024>>>(N);
    k_fill<<<(Etot + 255) / 256, 256>>>(ei, E, N);
    k_soft<<<(N * 8 + 255) / 256, 256>>>(N);
    k_agg<<<(N + 3) / 4, 256>>>(bias, out, N);
}